// round 14
// baseline (speedup 1.0000x reference)
#include <cuda_runtime.h>
#include <cuda_bf16.h>
#include <math.h>

#define BB   64
#define LL   65536
#define NW   2047
#define WPB  128
#define BPB  16
#define SPAN_MAX 4128
#define HID  512
#define DM   256
#define SD   321

// ---------------- scratch (__device__ globals; no allocation allowed) -------
__device__ unsigned int g_hist_parts[BB * BPB * 256];
__device__ float g_went[BB * NW];

// ---------------- Kernel A: windowed entropies + global hist partials -------
__global__ void __launch_bounds__(256) win_kernel(const int* __restrict__ x) {
    const int b    = blockIdx.y;
    const int blk  = blockIdx.x;
    const int tid  = threadIdx.x;
    const int lane = tid & 31;
    const int warp = tid >> 5;

    const int wstart = blk * WPB;
    const int wcount = min(WPB, NW - wstart);
    const int span   = (wcount - 1) * 32 + 64;
    const long base  = (long)b * LL + (long)blk * (WPB * 32);

    __shared__ __align__(16) unsigned char s_x[SPAN_MAX + 32];
    __shared__ unsigned int  s_hist[8][64];   // packed u8 counts (4 per word)
    __shared__ unsigned int  s_part[256];
    __shared__ float         s_lut[65];

    if (tid < 256) s_part[tid] = 0u;
    if (tid <= 64) {
        if (tid == 0) s_lut[0] = 0.0f;
        else {
            float p = (float)tid * (1.0f / 64.0f);
            float t = -(p * log2f(p + 1e-10f));
            s_lut[tid] = t / (float)tid;
        }
    }
    {
        const int4* xv = (const int4*)(x + base);
        uchar4* sv = (uchar4*)s_x;
        const int n4 = span >> 2;
        for (int i = tid; i < n4; i += 256) {
            int4 v = xv[i];
            sv[i] = make_uchar4((unsigned char)min(max(v.x, 0), 255),
                                (unsigned char)min(max(v.y, 0), 255),
                                (unsigned char)min(max(v.z, 0), 255),
                                (unsigned char)min(max(v.w, 0), 255));
        }
    }
    __syncthreads();

    for (int i = tid; i < 4096; i += 256)
        atomicAdd(&s_part[s_x[i]], 1u);

    unsigned int* hist = s_hist[warp];
    for (int wi = warp; wi < wcount; wi += 8) {
        const int off = wi * 32;
        hist[lane]      = 0u;
        hist[lane + 32] = 0u;
        __syncwarp();
        const int va = s_x[off + lane];
        const int vb = s_x[off + 32 + lane];
        atomicAdd(&hist[va >> 2], 1u << ((va & 3) << 3));
        atomicAdd(&hist[vb >> 2], 1u << ((vb & 3) << 3));
        __syncwarp();
        const unsigned ca = (hist[va >> 2] >> ((va & 3) << 3)) & 0xFFu;
        const unsigned cb = (hist[vb >> 2] >> ((vb & 3) << 3)) & 0xFFu;
        float h = s_lut[ca] + s_lut[cb];
        #pragma unroll
        for (int o = 16; o; o >>= 1) h += __shfl_xor_sync(0xffffffffu, h, o);
        if (lane == 0) g_went[b * NW + wstart + wi] = h;
    }

    __syncthreads();
    if (tid < 256) g_hist_parts[(b * BPB + blk) * 256 + tid] = s_part[tid];
}

// ---------------- Kernel B: per-row fused feat + full MLP --------------------
// grid = 64 (one block per batch row), 512 threads. Entire row pipeline is
// block-local: feats -> z1 -> LN -> relu -> z2 -> LN -> relu -> out.
// No inter-block communication of any kind.
__global__ void __launch_bounds__(512, 1) row_mlp_kernel(
    const float* __restrict__ W1, const float* __restrict__ b1,
    const float* __restrict__ g1, const float* __restrict__ be1,
    const float* __restrict__ W2, const float* __restrict__ b2,
    const float* __restrict__ g2, const float* __restrict__ be2,
    const float* __restrict__ W3, const float* __restrict__ b3,
    float* __restrict__ out) {
    const int b    = blockIdx.x;
    const int tid  = threadIdx.x;
    const int lane = tid & 31;
    const int wid  = tid >> 5;

    __shared__ __align__(16) float s_feat[324];   // 321 used
    __shared__ __align__(16) float s_a1[512];     // also reused as s_p
    __shared__ __align__(16) float s_a2[512];
    __shared__ float        s_lev[64];
    __shared__ float        s_red[16];
    __shared__ float        s_tot;
    __shared__ unsigned int s_cnt[64];

    // ---- features ----
    if (tid < 256) {
        unsigned int c = 0;
        #pragma unroll
        for (int p = 0; p < BPB; p++)
            c += g_hist_parts[(b * BPB + p) * 256 + tid];
        const float nh = (float)c * (1.0f / 65536.0f);
        s_feat[tid] = nh;
        float term = -(nh * log2f(nh + 1e-10f));
        #pragma unroll
        for (int o = 16; o; o >>= 1) term += __shfl_xor_sync(0xffffffffu, term, o);
        if (lane == 0) s_red[wid] = term;
    }
    if (tid < 64) {
        s_lev[tid] = (tid == 63) ? 8.0f : (float)tid * (8.0f / 63.0f);
        s_cnt[tid] = 0u;
    }
    __syncthreads();
    if (tid == 0) {
        float u = 0.f;
        #pragma unroll
        for (int i = 0; i < 8; i++) u += s_red[i];
        s_feat[256] = u;
    }
    // CDF buckets (all 512 threads)
    for (int i = tid; i < NW; i += 512) {
        const float h = g_went[b * NW + i];
        int j = (int)(h * 7.875f);
        j = min(max(j, 0), 63);
        while (j > 0 && h <= s_lev[j - 1]) j--;
        while (j < 63 && h > s_lev[j]) j++;
        const unsigned m = __match_any_sync(__activemask(), j);
        if ((m & ((1u << lane) - 1u)) == 0u)
            atomicAdd(&s_cnt[j], (unsigned)__popc(m));
    }
    __syncthreads();
    #pragma unroll
    for (int o = 1; o < 64; o <<= 1) {
        unsigned v = 0;
        if (tid < 64 && tid >= o) v = s_cnt[tid - o];
        __syncthreads();
        if (tid < 64) s_cnt[tid] += v;
        __syncthreads();
    }
    if (tid < 64) s_feat[257 + tid] = (float)s_cnt[tid] / 2047.0f;
    __syncthreads();

    // ---- layer 1: z1[c] = feats . W1[:,c] + b1[c]  (K=321, N=512) ----
    float z;
    {
        float acc = 0.f;
        const float* w = W1 + tid;
        #pragma unroll 4
        for (int k = 0; k < SD; k++)
            acc = fmaf(s_feat[k], w[(long)k * HID], acc);
        z = acc + b1[tid];
    }
    // ---- LN + relu -> s_a1 ----
    {
        float t = z;
        #pragma unroll
        for (int o = 16; o; o >>= 1) t += __shfl_xor_sync(0xffffffffu, t, o);
        if (lane == 0) s_red[wid] = t;
        __syncthreads();
        if (tid == 0) {
            float u = 0.f;
            #pragma unroll
            for (int i = 0; i < 16; i++) u += s_red[i];
            s_tot = u;
        }
        __syncthreads();
        const float mu = s_tot * (1.0f / 512.0f);
        const float d = z - mu;
        float v = d * d;
        #pragma unroll
        for (int o = 16; o; o >>= 1) v += __shfl_xor_sync(0xffffffffu, v, o);
        if (lane == 0) s_red[wid] = v;
        __syncthreads();
        if (tid == 0) {
            float u = 0.f;
            #pragma unroll
            for (int i = 0; i < 16; i++) u += s_red[i];
            s_tot = u;
        }
        __syncthreads();
        const float rstd = rsqrtf(s_tot * (1.0f / 512.0f) + 1e-5f);
        s_a1[tid] = fmaxf(d * rstd * g1[tid] + be1[tid], 0.0f);
    }
    __syncthreads();

    // ---- layer 2: z2[c] = a1 . W2[:,c] + b2[c]  (K=512, N=512) ----
    {
        float acc = 0.f;
        const float* w = W2 + tid;
        #pragma unroll 8
        for (int k = 0; k < HID; k++)
            acc = fmaf(s_a1[k], w[(long)k * HID], acc);
        z = acc + b2[tid];
    }
    // ---- LN + relu -> s_a2 ----
    {
        float t = z;
        #pragma unroll
        for (int o = 16; o; o >>= 1) t += __shfl_xor_sync(0xffffffffu, t, o);
        if (lane == 0) s_red[wid] = t;
        __syncthreads();
        if (tid == 0) {
            float u = 0.f;
            #pragma unroll
            for (int i = 0; i < 16; i++) u += s_red[i];
            s_tot = u;
        }
        __syncthreads();
        const float mu = s_tot * (1.0f / 512.0f);
        const float d = z - mu;
        float v = d * d;
        #pragma unroll
        for (int o = 16; o; o >>= 1) v += __shfl_xor_sync(0xffffffffu, v, o);
        if (lane == 0) s_red[wid] = v;
        __syncthreads();
        if (tid == 0) {
            float u = 0.f;
            #pragma unroll
            for (int i = 0; i < 16; i++) u += s_red[i];
            s_tot = u;
        }
        __syncthreads();
        const float rstd = rsqrtf(s_tot * (1.0f / 512.0f) + 1e-5f);
        s_a2[tid] = fmaxf(d * rstd * g2[tid] + be2[tid], 0.0f);
    }
    __syncthreads();

    // ---- layer 3: out[c] = a2 . W3[:,c] + b3[c]  (K=512, N=256) ----
    // split-k across thread pairs: thread t handles col (t&255), k-half (t>>8)
    {
        const int c    = tid & 255;
        const int kofs = (tid >> 8) * 256;
        float acc = 0.f;
        const float* w = W3 + (long)kofs * DM + c;
        #pragma unroll 8
        for (int k = 0; k < 256; k++)
            acc = fmaf(s_a2[kofs + k], w[(long)k * DM], acc);
        s_a1[tid] = acc;          // reuse as partial buffer
    }
    __syncthreads();
    if (tid < 256)
        out[b * DM + tid] = s_a1[tid] + s_a1[tid + 256] + b3[tid];
}

// ---------------- launch ----------------------------------------------------
extern "C" void kernel_launch(void* const* d_in, const int* in_sizes, int n_in,
                              void* d_out, int out_size) {
    const int*   x   = (const int*)d_in[0];
    const float* W1  = (const float*)d_in[1];
    const float* b1  = (const float*)d_in[2];
    const float* g1  = (const float*)d_in[3];
    const float* be1 = (const float*)d_in[4];
    const float* W2  = (const float*)d_in[5];
    const float* b2  = (const float*)d_in[6];
    const float* g2  = (const float*)d_in[7];
    const float* be2 = (const float*)d_in[8];
    const float* W3  = (const float*)d_in[9];
    const float* b3  = (const float*)d_in[10];
    float* out = (float*)d_out;

    win_kernel<<<dim3(BPB, BB), 256>>>(x);
    row_mlp_kernel<<<BB, 512>>>(W1, b1, g1, be1, W2, b2, g2, be2, W3, b3, out);
}